// round 1
// baseline (speedup 1.0000x reference)
#include <cuda_runtime.h>
#include <math.h>

// LSTMCell fused: pre = x@Wi^T + h@Wh^T + bi  (per gate), then elementwise LSTM.
// Shapes: x[B,D], h[B,H], c[B,H], Wi[4,H,D], bi[4,H], Wh[4,H,H]; B=16384, D=H=1024.
// Output (pytree order): o [B,H], new_h [B,H], new_c [B,H]  -> 3*B*H floats.
//
// One fused kernel. Block tile: 128 rows (batch) x 128 cols, where the 128 cols
// are {gate 0..3} x {32 h columns}. K = 2048 (1024 from x/Wi then 1024 from h/Wh).
// Epilogue: accumulators -> shared transpose -> gates recombined -> outputs.

#define BM 128
#define BN 128        // 4 gates * 32 h
#define BK 32
#define PAD 132       // row stride in floats for shared tiles (conflict padding)

#define Bsz 16384
#define Hd  1024
#define Dd  1024

__global__ __launch_bounds__(256, 2) void lstm_fused_kernel(
    const float* __restrict__ x,  const float* __restrict__ hin,
    const float* __restrict__ c,  const float* __restrict__ Wi,
    const float* __restrict__ bi, const float* __restrict__ Wh,
    float* __restrict__ out)
{
    // union: mainloop uses As[BK][PAD] + Bs[BK][PAD]; epilogue reuses as Ps[64][PAD]
    __shared__ __align__(16) float smem[2 * BK * PAD];
    __shared__ float bias_s[128];

    float* As = smem;             // [BK][PAD], k-major (transposed store)
    float* Bs = smem + BK * PAD;  // [BK][PAD]

    const int tid = threadIdx.x;
    const int bx = blockIdx.x;    // h tile: 32 h-columns
    const int by = blockIdx.y;    // batch tile: 128 rows
    const int h0 = bx * 32;
    const int row0 = by * 128;

    if (tid < 128) {
        int gate = tid >> 5, hh = tid & 31;
        bias_s[tid] = bi[gate * Hd + h0 + hh];
    }

    const int tx = tid & 15;      // 0..15 -> 8 output cols each
    const int ty = tid >> 4;      // 0..15 -> 8 output rows each

    float acc[8][8];
    #pragma unroll
    for (int i = 0; i < 8; i++)
        #pragma unroll
        for (int j = 0; j < 8; j++) acc[i][j] = 0.f;

    const int k4 = tid & 7;       // which float4 along k (8 x 4 = 32 = BK)
    const int r0 = tid >> 3;      // 0..31

    for (int kt = 0; kt < 2048; kt += BK) {
        const float* Aptr;
        const float* Wptr;
        int kl;
        if (kt < 1024) { Aptr = x;   Wptr = Wi; kl = kt; }
        else           { Aptr = hin; Wptr = Wh; kl = kt - 1024; }

        // ---- load A tile: As[k][m], m = batch row within tile ----
        #pragma unroll
        for (int it = 0; it < 4; it++) {
            int m = r0 + 32 * it;
            float4 v = *reinterpret_cast<const float4*>(
                Aptr + (size_t)(row0 + m) * Dd + kl + k4 * 4);
            As[(k4 * 4 + 0) * PAD + m] = v.x;
            As[(k4 * 4 + 1) * PAD + m] = v.y;
            As[(k4 * 4 + 2) * PAD + m] = v.z;
            As[(k4 * 4 + 3) * PAD + m] = v.w;
        }
        // ---- load B tile: Bs[k][cc], cc = gate*32 + hh_local ----
        #pragma unroll
        for (int gate = 0; gate < 4; gate++) {
            int cc = r0 + 32 * gate;              // (cc>>5)==gate, (cc&31)==r0
            int wrow = gate * Hd + h0 + r0;       // row in [4H, K] weight view
            float4 v = *reinterpret_cast<const float4*>(
                Wptr + (size_t)wrow * 1024 + kl + k4 * 4);
            Bs[(k4 * 4 + 0) * PAD + cc] = v.x;
            Bs[(k4 * 4 + 1) * PAD + cc] = v.y;
            Bs[(k4 * 4 + 2) * PAD + cc] = v.z;
            Bs[(k4 * 4 + 3) * PAD + cc] = v.w;
        }
        __syncthreads();

        #pragma unroll 4
        for (int kk = 0; kk < BK; kk++) {
            float4 a0 = *reinterpret_cast<const float4*>(&As[kk * PAD + ty * 8]);
            float4 a1 = *reinterpret_cast<const float4*>(&As[kk * PAD + ty * 8 + 4]);
            float4 b0 = *reinterpret_cast<const float4*>(&Bs[kk * PAD + tx * 8]);
            float4 b1 = *reinterpret_cast<const float4*>(&Bs[kk * PAD + tx * 8 + 4]);
            float a[8] = {a0.x, a0.y, a0.z, a0.w, a1.x, a1.y, a1.z, a1.w};
            float b[8] = {b0.x, b0.y, b0.z, b0.w, b1.x, b1.y, b1.z, b1.w};
            #pragma unroll
            for (int i = 0; i < 8; i++)
                #pragma unroll
                for (int j = 0; j < 8; j++)
                    acc[i][j] = fmaf(a[i], b[j], acc[i][j]);
        }
        __syncthreads();
    }

    // ---- fused LSTM epilogue via shared transpose, two 64-row passes ----
    float* Ps = smem;  // [64][PAD]
    const size_t BH = (size_t)Bsz * Hd;

    #pragma unroll
    for (int p = 0; p < 2; p++) {
        if ((ty >> 3) == p) {
            int tyl = ty & 7;
            #pragma unroll
            for (int i = 0; i < 8; i++)
                #pragma unroll
                for (int j = 0; j < 8; j++)
                    Ps[(tyl * 8 + i) * PAD + tx * 8 + j] = acc[i][j];
        }
        __syncthreads();

        int r = tid >> 2;            // 0..63: local row
        int hhs = (tid & 3) * 8;     // 8 consecutive h-columns
        int bg = row0 + p * 64 + r;  // global batch row
        #pragma unroll
        for (int q = 0; q < 8; q++) {
            int hh = hhs + q;
            float iv = Ps[r * PAD + hh]      + bias_s[hh];
            float fv = Ps[r * PAD + 32 + hh] + bias_s[32 + hh];
            float gv = Ps[r * PAD + 64 + hh] + bias_s[64 + hh];
            float ov = Ps[r * PAD + 96 + hh] + bias_s[96 + hh];
            float is = 1.f / (1.f + __expf(-iv));
            float fs = 1.f / (1.f + __expf(-fv));
            float gt = tanhf(gv);
            float os = 1.f / (1.f + __expf(-ov));
            size_t idx = (size_t)bg * Hd + (h0 + hh);
            float cv = c[idx];
            float nc = fs * cv + is * gt;
            float nh = os * tanhf(nc);
            out[idx]          = os;   // o
            out[BH + idx]     = nh;   // new_h
            out[2 * BH + idx] = nc;   // new_c
        }
        __syncthreads();
    }
}

extern "C" void kernel_launch(void* const* d_in, const int* in_sizes, int n_in,
                              void* d_out, int out_size) {
    const float* x   = (const float*)d_in[0];
    const float* h   = (const float*)d_in[1];
    const float* c   = (const float*)d_in[2];
    const float* Wi  = (const float*)d_in[3];
    const float* bi  = (const float*)d_in[4];
    const float* Wh  = (const float*)d_in[5];
    float* out = (float*)d_out;

    dim3 grid(Hd / 32, Bsz / 128);   // (32, 128)
    lstm_fused_kernel<<<grid, 256>>>(x, h, c, Wi, bi, Wh, out);
}

// round 2
// speedup vs baseline: 3.1850x; 3.1850x over previous
#include <cuda_runtime.h>
#include <math.h>
#include <stdint.h>

// LSTMCell fused, TF32 tensor-core version.
// pre[B,4H] = x@Wi^T + h@Wh^T + bi, then elementwise LSTM.
// B=16384, D=H=1024. Output: o, new_h, new_c (each [B,H] fp32).
//
// CTA tile: 128 (batch) x 128 (4 gates x 32 h), K=2048 in BK=16 stages,
// cp.async double-buffered. 8 warps = 4(M) x 2(N), warp tile 32x64,
// mma.sync.m16n8k8.tf32 with ldmatrix fragment loads. Fused LSTM epilogue
// via smem transpose (two 64-row passes).

#define Bsz 16384
#define Hd  1024
#define BK  16
#define KST 20          // BK + 4 floats pad (rows stay 16B aligned, LDSM conflict-free)

__device__ __forceinline__ uint32_t cvta_s(const void* p) {
    return (uint32_t)__cvta_generic_to_shared(p);
}
__device__ __forceinline__ uint32_t f2tf32(uint32_t x) {
    uint32_t r;
    asm("cvt.rna.tf32.f32 %0, %1;" : "=r"(r) : "f"(__uint_as_float(x)));
    return r;
}

__global__ __launch_bounds__(256, 2) void lstm_tf32_kernel(
    const float* __restrict__ x,  const float* __restrict__ hin,
    const float* __restrict__ c,  const float* __restrict__ Wi,
    const float* __restrict__ bi, const float* __restrict__ Wh,
    float* __restrict__ out)
{
    // 4 tiles of 128 rows x KST floats: As0, As1, Bs0, Bs1 = 10240 floats = 40KB
    __shared__ __align__(16) float smem[4 * 128 * KST];
    __shared__ float bias_s[128];

    const int tid  = threadIdx.x;
    const int lane = tid & 31;
    const int warp = tid >> 5;
    const int h0   = blockIdx.x * 32;
    const int row0 = blockIdx.y * 128;

    float* As[2] = { smem,            smem + 128 * KST };
    float* Bs[2] = { smem + 2*128*KST, smem + 3*128*KST };

    if (tid < 128) bias_s[tid] = bi[(tid >> 5) * Hd + h0 + (tid & 31)];

    const int wm  = warp & 3;          // 0..3 along M
    const int wn  = warp >> 2;         // 0..1 along N
    const int M0  = wm * 32;
    const int N0w = wn * 64;

    // ldmatrix per-thread address components (x4 = 4 blocks of 8x4 b32)
    const int blk = lane >> 3, r8 = lane & 7;
    const int aRow = (blk & 1) * 8 + r8;   // A blocks: rows {0,8} x cols {0,4}
    const int aCol = (blk >> 1) * 4;
    const int bRow = (blk >> 1) * 8 + r8;  // B blocks: cols {0,4} x rows {0,8}
    const int bCol = (blk & 1) * 4;

    float acc[2][8][4] = {};

    auto prefetch = [&](int s, int b) {
        const float* Ap; const float* Wp; int kl;
        if (s < 64) { Ap = x;   Wp = Wi; kl = s * BK; }
        else        { Ap = hin; Wp = Wh; kl = (s - 64) * BK; }
        uint32_t sa = cvta_s(As[b]), sb = cvta_s(Bs[b]);
        #pragma unroll
        for (int it = 0; it < 2; it++) {                // A: 512 x 16B chunks
            int ci = tid + it * 256;
            int row = ci >> 2, off = (ci & 3) << 2;
            uint32_t d = sa + (uint32_t)(row * KST + off) * 4u;
            const float* sp = Ap + (size_t)(row0 + row) * 1024 + kl + off;
            asm volatile("cp.async.cg.shared.global [%0], [%1], 16;" :: "r"(d), "l"(sp));
        }
        #pragma unroll
        for (int it = 0; it < 2; it++) {                // B (weights)
            int ci = tid + it * 256;
            int row = ci >> 2, off = (ci & 3) << 2;
            int wrow = (row >> 5) * 1024 + h0 + (row & 31);   // gate*H + h
            uint32_t d = sb + (uint32_t)(row * KST + off) * 4u;
            const float* sp = Wp + (size_t)wrow * 1024 + kl + off;
            asm volatile("cp.async.cg.shared.global [%0], [%1], 16;" :: "r"(d), "l"(sp));
        }
        asm volatile("cp.async.commit_group;");
    };

    prefetch(0, 0);

    for (int s = 0; s < 128; s++) {
        if (s + 1 < 128) {
            prefetch(s + 1, (s + 1) & 1);
            asm volatile("cp.async.wait_group 1;");
        } else {
            asm volatile("cp.async.wait_group 0;");
        }
        __syncthreads();

        const int b = s & 1;
        const uint32_t sa = cvta_s(As[b]), sb = cvta_s(Bs[b]);

        #pragma unroll
        for (int ks = 0; ks < 2; ks++) {          // two k8 steps per stage
            uint32_t a[2][4];
            #pragma unroll
            for (int i = 0; i < 2; i++) {
                uint32_t addr = sa + (uint32_t)((M0 + i*16 + aRow) * KST + ks*8 + aCol) * 4u;
                asm volatile("ldmatrix.sync.aligned.m8n8.x4.shared.b16 {%0,%1,%2,%3}, [%4];"
                    : "=r"(a[i][0]), "=r"(a[i][1]), "=r"(a[i][2]), "=r"(a[i][3])
                    : "r"(addr));
            }
            uint32_t bf[4][4];
            #pragma unroll
            for (int j2 = 0; j2 < 4; j2++) {
                uint32_t addr = sb + (uint32_t)((N0w + j2*16 + bRow) * KST + ks*8 + bCol) * 4u;
                asm volatile("ldmatrix.sync.aligned.m8n8.x4.shared.b16 {%0,%1,%2,%3}, [%4];"
                    : "=r"(bf[j2][0]), "=r"(bf[j2][1]), "=r"(bf[j2][2]), "=r"(bf[j2][3])
                    : "r"(addr));
            }
            #pragma unroll
            for (int i = 0; i < 2; i++)
                #pragma unroll
                for (int r = 0; r < 4; r++) a[i][r] = f2tf32(a[i][r]);
            #pragma unroll
            for (int j2 = 0; j2 < 4; j2++)
                #pragma unroll
                for (int r = 0; r < 4; r++) bf[j2][r] = f2tf32(bf[j2][r]);

            #pragma unroll
            for (int i = 0; i < 2; i++)
                #pragma unroll
                for (int j = 0; j < 8; j++) {
                    uint32_t b0 = bf[j >> 1][(j & 1) * 2];
                    uint32_t b1 = bf[j >> 1][(j & 1) * 2 + 1];
                    asm volatile(
                        "mma.sync.aligned.m16n8k8.row.col.f32.tf32.tf32.f32 "
                        "{%0,%1,%2,%3}, {%4,%5,%6,%7}, {%8,%9}, {%0,%1,%2,%3};"
                        : "+f"(acc[i][j][0]), "+f"(acc[i][j][1]),
                          "+f"(acc[i][j][2]), "+f"(acc[i][j][3])
                        : "r"(a[i][0]), "r"(a[i][1]), "r"(a[i][2]), "r"(a[i][3]),
                          "r"(b0), "r"(b1));
                }
        }
        __syncthreads();
    }

    // ---- fused LSTM epilogue: smem transpose, two 64-row passes ----
    float* Ps = smem;                      // [64][132] = 8448 floats, fits
    const size_t BH = (size_t)Bsz * Hd;
    const int fr = lane >> 2, fc = lane & 3;

    #pragma unroll
    for (int p = 0; p < 2; p++) {
        if ((wm >> 1) == p) {
            int mb = (wm & 1) * 32;
            #pragma unroll
            for (int i = 0; i < 2; i++)
                #pragma unroll
                for (int j = 0; j < 8; j++) {
                    int rr = mb + i * 16 + fr;
                    int cc = N0w + j * 8 + 2 * fc;
                    Ps[rr * 132 + cc]           = acc[i][j][0];
                    Ps[rr * 132 + cc + 1]       = acc[i][j][1];
                    Ps[(rr + 8) * 132 + cc]     = acc[i][j][2];
                    Ps[(rr + 8) * 132 + cc + 1] = acc[i][j][3];
                }
        }
        __syncthreads();

        int rr  = tid >> 2;
        int hhs = (tid & 3) * 8;
        int bg  = row0 + p * 64 + rr;
        #pragma unroll
        for (int q = 0; q < 8; q++) {
            int hh = hhs + q;
            float iv = Ps[rr * 132 + hh]      + bias_s[hh];
            float fv = Ps[rr * 132 + 32 + hh] + bias_s[32 + hh];
            float gv = Ps[rr * 132 + 64 + hh] + bias_s[64 + hh];
            float ov = Ps[rr * 132 + 96 + hh] + bias_s[96 + hh];
            float is = 1.f / (1.f + __expf(-iv));
            float fs = 1.f / (1.f + __expf(-fv));
            float gt = tanhf(gv);
            float os = 1.f / (1.f + __expf(-ov));
            size_t idx = (size_t)bg * Hd + (h0 + hh);
            float cv = c[idx];
            float nc = fs * cv + is * gt;
            float nh = os * tanhf(nc);
            out[idx]          = os;
            out[BH + idx]     = nh;
            out[2 * BH + idx] = nc;
        }
        __syncthreads();
    }
}

extern "C" void kernel_launch(void* const* d_in, const int* in_sizes, int n_in,
                              void* d_out, int out_size) {
    const float* x  = (const float*)d_in[0];
    const float* h  = (const float*)d_in[1];
    const float* c  = (const float*)d_in[2];
    const float* Wi = (const float*)d_in[3];
    const float* bi = (const float*)d_in[4];
    const float* Wh = (const float*)d_in[5];
    float* out = (float*)d_out;

    dim3 grid(Hd / 32, Bsz / 128);   // (32, 128)
    lstm_tf32_kernel<<<grid, 256>>>(x, h, c, Wi, bi, Wh, out);
}

// round 4
// speedup vs baseline: 3.8277x; 1.2018x over previous
#include <cuda_runtime.h>
#include <cuda_fp16.h>
#include <math.h>
#include <stdint.h>

// LSTMCell fused, fp16 mma.sync.m16n8k16 version (sm_103 virtual arch — no tcgen05).
// Pre-pass converts x,h,Wi,Wh to fp16 scratch; main kernel does
// pre[B,4H] = x@Wi^T + h@Wh^T + bi on tensor cores + fused LSTM epilogue.
// B=16384, D=H=1024. Output: o, new_h, new_c (each [B,H] fp32).

#define Bsz 16384
#define Hd  1024
#define BKH 64            // K per stage, in halves
#define SROW 72           // smem row stride in halves (64 + 8 pad), 144B
#define STAGE_HALVES (128 * SROW)          // one tile (A or B): 9216 halves
#define STAGE_BYTES  (2 * 2 * STAGE_HALVES) // A+B per stage: 36864 B

// fp16 scratch: x|h (2 x 16777216), Wi|Wh (2 x 4194304)
__device__ __half g_xh[33554432];
__device__ __half g_ww[8388608];

__global__ __launch_bounds__(256) void cvt_kernel(const float* __restrict__ src,
                                                  int sel, int n8) {
    int i = blockIdx.x * blockDim.x + threadIdx.x;
    if (i >= n8) return;
    __half* dst = (sel == 0) ? g_xh
                : (sel == 1) ? g_xh + 16777216
                : (sel == 2) ? g_ww
                             : g_ww + 4194304;
    const float4 v0 = reinterpret_cast<const float4*>(src)[i * 2];
    const float4 v1 = reinterpret_cast<const float4*>(src)[i * 2 + 1];
    __half2 h[4];
    h[0] = __floats2half2_rn(v0.x, v0.y);
    h[1] = __floats2half2_rn(v0.z, v0.w);
    h[2] = __floats2half2_rn(v1.x, v1.y);
    h[3] = __floats2half2_rn(v1.z, v1.w);
    reinterpret_cast<uint4*>(dst)[i] = *reinterpret_cast<uint4*>(h);
}

static __device__ __forceinline__ uint32_t cvta_s(const void* p) {
    return (uint32_t)__cvta_generic_to_shared(p);
}
static __device__ __forceinline__ void cp_async16(uint32_t dst, const void* src) {
    asm volatile("cp.async.cg.shared.global [%0], [%1], 16;" :: "r"(dst), "l"(src));
}

__global__ __launch_bounds__(256, 2) void lstm_fp16_kernel(
    const float* __restrict__ c, const float* __restrict__ bi,
    float* __restrict__ out)
{
    extern __shared__ __align__(16) char smem[];
    __half* stage0 = (__half*)smem;                     // A0,B0,A1,B1
    float*  bias_s = (float*)(smem + 2 * STAGE_BYTES);  // 128 floats

    const int tid  = threadIdx.x;
    const int lane = tid & 31;
    const int warp = tid >> 5;
    const int h0   = blockIdx.x * 32;   // 32 h-cols
    const int row0 = blockIdx.y * 128;  // 128 batch rows

    if (tid < 128) bias_s[tid] = bi[(tid >> 5) * Hd + h0 + (tid & 31)];

    const int wm  = warp & 3;          // M: 4 x 32
    const int wn  = warp >> 2;         // N: 2 x 64
    const int M0  = wm * 32;
    const int N0w = wn * 64;

    // ldmatrix lane mapping (x4 over a 16x16 b16 tile):
    // t0-7 -> (rows 0-7, k 0-7), t8-15 -> (rows 8-15, k 0-7),
    // t16-23 -> (rows 0-7, k 8-15), t24-31 -> (rows 8-15, k 8-15)
    const int blk = lane >> 3, r8 = lane & 7;
    const int lmRow = (blk & 1) * 8 + r8;
    const int lmCol = (blk >> 1) * 8;

    float acc[2][8][4] = {};

    auto prefetch = [&](int s, int b) {
        const __half* Ap = (s < 16) ? g_xh : g_xh + 16777216;
        const __half* Wp = (s < 16) ? g_ww : g_ww + 4194304;
        const int kl = (s & 15) * BKH;
        __half* As = stage0 + (size_t)b * 2 * STAGE_HALVES;
        __half* Bs = As + STAGE_HALVES;
        const uint32_t sa = cvta_s(As), sb = cvta_s(Bs);
        // A: 128 rows x 128B = 1024 x 16B chunks; 4 per thread
        #pragma unroll
        for (int it = 0; it < 4; it++) {
            int ci = tid + it * 256;
            int row = ci >> 3, j = ci & 7;       // j: 16B chunk within row
            cp_async16(sa + (uint32_t)(row * SROW + j * 8) * 2u,
                       Ap + (size_t)(row0 + row) * 1024 + kl + j * 8);
        }
        // B: col cc = gate*32 + hh ; weight row = gate*1024 + h0 + hh
        #pragma unroll
        for (int it = 0; it < 4; it++) {
            int ci = tid + it * 256;
            int cc = ci >> 3, j = ci & 7;
            int wrow = (cc >> 5) * 1024 + h0 + (cc & 31);
            cp_async16(sb + (uint32_t)(cc * SROW + j * 8) * 2u,
                       Wp + (size_t)wrow * 1024 + kl + j * 8);
        }
        asm volatile("cp.async.commit_group;");
    };

    prefetch(0, 0);

    for (int s = 0; s < 32; s++) {
        if (s + 1 < 32) {
            prefetch(s + 1, (s + 1) & 1);
            asm volatile("cp.async.wait_group 1;" ::: "memory");
        } else {
            asm volatile("cp.async.wait_group 0;" ::: "memory");
        }
        __syncthreads();

        const __half* As = stage0 + (size_t)(s & 1) * 2 * STAGE_HALVES;
        const uint32_t sa = cvta_s(As), sb = cvta_s(As + STAGE_HALVES);

        #pragma unroll
        for (int ks = 0; ks < 4; ks++) {           // four k16 steps per stage
            uint32_t a[2][4];
            #pragma unroll
            for (int i = 0; i < 2; i++) {
                uint32_t addr = sa + (uint32_t)((M0 + i*16 + lmRow) * SROW
                                                + ks*16 + lmCol) * 2u;
                asm volatile("ldmatrix.sync.aligned.m8n8.x4.shared.b16 {%0,%1,%2,%3}, [%4];"
                    : "=r"(a[i][0]), "=r"(a[i][1]), "=r"(a[i][2]), "=r"(a[i][3])
                    : "r"(addr));
            }
            uint32_t bf[4][4];
            #pragma unroll
            for (int j2 = 0; j2 < 4; j2++) {
                uint32_t addr = sb + (uint32_t)((N0w + j2*16 + lmRow) * SROW
                                                + ks*16 + lmCol) * 2u;
                asm volatile("ldmatrix.sync.aligned.m8n8.x4.shared.b16 {%0,%1,%2,%3}, [%4];"
                    : "=r"(bf[j2][0]), "=r"(bf[j2][1]), "=r"(bf[j2][2]), "=r"(bf[j2][3])
                    : "r"(addr));
            }
            #pragma unroll
            for (int i = 0; i < 2; i++)
                #pragma unroll
                for (int j = 0; j < 8; j++) {
                    // n8-block (j&1) of n16-group (j>>1): b = {r[j&1], r[2+(j&1)]}
                    uint32_t b0 = bf[j >> 1][j & 1];
                    uint32_t b1 = bf[j >> 1][2 + (j & 1)];
                    asm volatile(
                        "mma.sync.aligned.m16n8k16.row.col.f32.f16.f16.f32 "
                        "{%0,%1,%2,%3}, {%4,%5,%6,%7}, {%8,%9}, {%0,%1,%2,%3};"
                        : "+f"(acc[i][j][0]), "+f"(acc[i][j][1]),
                          "+f"(acc[i][j][2]), "+f"(acc[i][j][3])
                        : "r"(a[i][0]), "r"(a[i][1]), "r"(a[i][2]), "r"(a[i][3]),
                          "r"(b0), "r"(b1));
                }
        }
        __syncthreads();
    }

    // ---- fused LSTM epilogue: smem transpose, two 64-row passes ----
    float* Ps = (float*)smem;               // [64][132] floats = 33792B, fits
    const size_t BH = (size_t)Bsz * Hd;
    const int fr = lane >> 2, fc = lane & 3;

    #pragma unroll
    for (int p = 0; p < 2; p++) {
        if ((wm >> 1) == p) {
            int mb = (wm & 1) * 32;
            #pragma unroll
            for (int i = 0; i < 2; i++)
                #pragma unroll
                for (int j = 0; j < 8; j++) {
                    int rr = mb + i * 16 + fr;
                    int cc = N0w + j * 8 + 2 * fc;
                    Ps[rr * 132 + cc]           = acc[i][j][0];
                    Ps[rr * 132 + cc + 1]       = acc[i][j][1];
                    Ps[(rr + 8) * 132 + cc]     = acc[i][j][2];
                    Ps[(rr + 8) * 132 + cc + 1] = acc[i][j][3];
                }
        }
        __syncthreads();

        int rr  = tid >> 2;
        int hhs = (tid & 3) * 8;
        int bg  = row0 + p * 64 + rr;
        #pragma unroll
        for (int q = 0; q < 8; q++) {
            int hh = hhs + q;
            float iv = Ps[rr * 132 + hh]      + bias_s[hh];
            float fv = Ps[rr * 132 + 32 + hh] + bias_s[32 + hh];
            float gv = Ps[rr * 132 + 64 + hh] + bias_s[64 + hh];
            float ov = Ps[rr * 132 + 96 + hh] + bias_s[96 + hh];
            float is = 1.f / (1.f + __expf(-iv));
            float fs = 1.f / (1.f + __expf(-fv));
            float gt = tanhf(gv);
            float os = 1.f / (1.f + __expf(-ov));
            size_t idx = (size_t)bg * Hd + (h0 + hh);
            float cv = c[idx];
            float nc = fs * cv + is * gt;
            float nh = os * tanhf(nc);
            out[idx]          = os;
            out[BH + idx]     = nh;
            out[2 * BH + idx] = nc;
        }
        __syncthreads();
    }
}

extern "C" void kernel_launch(void* const* d_in, const int* in_sizes, int n_in,
                              void* d_out, int out_size) {
    const float* x  = (const float*)d_in[0];
    const float* h  = (const float*)d_in[1];
    const float* c  = (const float*)d_in[2];
    const float* Wi = (const float*)d_in[3];
    const float* bi = (const float*)d_in[4];
    const float* Wh = (const float*)d_in[5];
    float* out = (float*)d_out;

    // fp32 -> fp16 pre-pass (x, h, Wi, Wh)
    cvt_kernel<<<8192, 256>>>(x,  0, 16777216 / 8);
    cvt_kernel<<<8192, 256>>>(h,  1, 16777216 / 8);
    cvt_kernel<<<2048, 256>>>(Wi, 2, 4194304 / 8);
    cvt_kernel<<<2048, 256>>>(Wh, 3, 4194304 / 8);

    const int smem_bytes = 2 * STAGE_BYTES + 512;   // 74240 B
    static int configured = -1;
    if (configured < 0) {
        cudaFuncSetAttribute(lstm_fp16_kernel,
                             cudaFuncAttributeMaxDynamicSharedMemorySize, smem_bytes);
        configured = 1;
    }
    dim3 grid(Hd / 32, Bsz / 128);   // (32, 128) = 4096 CTAs
    lstm_fp16_kernel<<<grid, 256, smem_bytes>>>(c, bi, out);
}